// round 12
// baseline (speedup 1.0000x reference)
#include <cuda_runtime.h>
#include <cuda_bf16.h>
#include <cstdint>
#include <math.h>

#define NQ      32768
#define KC      8192
#define DD      256
#define MT      128           // queries per CTA
#define NTILE   128           // codes per tile
#define NTILES  (KC / NTILE)  // 64
#define WTH     1.0e-4f       // coarse trust window (>= 2x worst coarse error)
#define MAXC    8             // max stored candidates per query

// ---------------- device scratch (no cudaMalloc) ----------------------------
__device__ float g_cbsq[KC];
// codebook bf16, pre-swizzled tile-major: tile t occupies bytes [t*65536,(t+1)*65536)
__device__ __align__(128) unsigned char g_cb_tiled[KC * DD * 2];
__device__ int   g_listA[NQ];
__device__ int   g_cntA;
__device__ int   g_listB[NQ];
__device__ int   g_cntB;
__device__ int   g_cands[NQ * MAXC];
__device__ int   g_ncand[NQ];

// ---------------- smem layout (bytes) ---------------------------------------
#define SM_A     0             // 64KB z tile (4 dc chunks); triage overlay later
#define SM_B     65536         // 2 x 64KB tile buffers
#define SM_MBAR  196608        // 2 mbarriers
#define SM_TOTAL 196672

__device__ __forceinline__ uint32_t smem_u32(const void* p) {
    uint32_t a;
    asm("{ .reg .u64 t; cvta.to.shared.u64 t, %1; cvt.u32.u64 %0, t; }"
        : "=r"(a) : "l"(p));
    return a;
}
__device__ __forceinline__ uint32_t swz(uint32_t b) { return b ^ ((b >> 3) & 0x70); }

#define LDSM_X4(r0, r1, r2, r3, addr) \
    asm volatile("ldmatrix.sync.aligned.m8n8.x4.shared.b16 {%0,%1,%2,%3}, [%4];" \
                 : "=r"(r0), "=r"(r1), "=r"(r2), "=r"(r3) : "r"(addr))

#define MMA_BF16(c0, c1, c2, c3, a0, a1, a2, a3, b0, b1) \
    asm volatile("mma.sync.aligned.m16n8k16.row.col.f32.bf16.bf16.f32 " \
                 "{%0,%1,%2,%3}, {%4,%5,%6,%7}, {%8,%9}, {%0,%1,%2,%3};" \
                 : "+f"(c0), "+f"(c1), "+f"(c2), "+f"(c3) \
                 : "r"(a0), "r"(a1), "r"(a2), "r"(a3), "r"(b0), "r"(b1))

#define MBARRIER_INIT(mb, c) \
    asm volatile("mbarrier.init.shared.b64 [%0], %1;" :: "r"((uint32_t)(mb)), "r"((uint32_t)(c)) : "memory")
#define MBARRIER_EXPECT_TX(mb, bytes) \
    asm volatile("mbarrier.arrive.expect_tx.shared.b64 _, [%0], %1;" \
                 :: "r"((uint32_t)(mb)), "r"((uint32_t)(bytes)) : "memory")
#define CP_BULK(dst, src, bytes, mb) \
    asm volatile("cp.async.bulk.shared::cta.global.mbarrier::complete_tx::bytes [%0], [%1], %2, [%3];" \
                 :: "r"((uint32_t)(dst)), "l"(src), "r"((uint32_t)(bytes)), "r"((uint32_t)(mb)) : "memory")

#define MBARRIER_WAIT_PARITY(mb, ph) do {                                        \
    uint32_t _mb = (uint32_t)(mb), _ph = (uint32_t)(ph), _done;                  \
    asm volatile("{\n\t.reg .pred p;\n\t"                                        \
        "mbarrier.try_wait.parity.acquire.cta.shared::cta.b64 p, [%1], %2;\n\t"  \
        "selp.b32 %0, 1, 0, p;\n\t}"                                             \
        : "=r"(_done) : "r"(_mb), "r"(_ph) : "memory");                          \
    if (!_done) {                                                                \
        asm volatile("{\n\t.reg .pred P1;\n\t"                                   \
        "WL_%=:\n\t"                                                             \
        "mbarrier.try_wait.parity.acquire.cta.shared::cta.b64 P1, [%0], %1, 0x989680;\n\t" \
        "@P1 bra.uni WD_%=;\n\t"                                                 \
        "bra.uni WL_%=;\n\t"                                                     \
        "WD_%=:\n\t}" :: "r"(_mb), "r"(_ph) : "memory");                         \
    }                                                                            \
} while (0)

// ---------------------------------------------------------------------------
// Prep: codebook -> pre-swizzled tile-major bf16 + ||e||^2; zero counters.
// One warp per code.
// ---------------------------------------------------------------------------
__global__ void prep_kernel(const float* __restrict__ cb) {
    if (blockIdx.x == 0 && threadIdx.x == 0) { g_cntA = 0; g_cntB = 0; }
    int w = (blockIdx.x * blockDim.x + threadIdx.x) >> 5;
    int lane = threadIdx.x & 31;
    if (w >= KC) return;
    const float4* row = (const float4*)(cb + (size_t)w * DD);
    float s = 0.f;
    #pragma unroll
    for (int i = 0; i < 2; i++) {
        int f = lane + i * 32;               // float4 index 0..63 (dim = 4f)
        float4 v = row[f];
        s += v.x * v.x + v.y * v.y + v.z * v.z + v.w * v.w;
        __nv_bfloat162 h0 = {__float2bfloat16_rn(v.x), __float2bfloat16_rn(v.y)};
        __nv_bfloat162 h1 = {__float2bfloat16_rn(v.z), __float2bfloat16_rn(v.w)};
        uint2 hu = {*(uint32_t*)&h0, *(uint32_t*)&h1};
        // tile-major destination: block = (tile*4 + dc)*16KB,
        // inner = swz(code_in_tile*128 + (dim%64)*2)
        int dc = f >> 4;                     // dim chunk 0..3
        uint32_t blk = ((uint32_t)(w >> 7) * 4 + dc) * 16384u;
        uint32_t inner = swz((uint32_t)((w & 127) * 128 + (f & 15) * 8));
        *(uint2*)(g_cb_tiled + blk + inner) = hu;
    }
    #pragma unroll
    for (int off = 16; off; off >>= 1) s += __shfl_xor_sync(0xffffffffu, s, off);
    if (lane == 0) g_cbsq[w] = s;
}

// ---------------------------------------------------------------------------
// Main: single-pass bf16 HMMA + per-slot top-2 + window triage.
// B streamed via cp.async.bulk (one 64KB copy per tile), double-buffered.
// 512 threads = 16 warps (4M x 4N). CTA: 128 queries x all 8192 codes.
// ---------------------------------------------------------------------------
__global__ void __launch_bounds__(512, 1)
vq_mma_kernel(const float* __restrict__ z, float* __restrict__ out) {
    extern __shared__ char smem[];
    const uint32_t sb = smem_u32(smem);
    const int tid  = threadIdx.x;
    const int wid  = tid >> 5;
    const int lane = tid & 31;
    const int wm   = wid >> 2;
    const int wn   = wid & 3;
    const int qbase = blockIdx.x * MT;

    // init barriers, then kick off tiles 0 and 1
    if (tid == 0) {
        MBARRIER_INIT(sb + SM_MBAR + 0, 1);
        MBARRIER_INIT(sb + SM_MBAR + 8, 1);
    }
    __syncthreads();
    if (tid == 0) {
        #pragma unroll
        for (int t = 0; t < 2; t++) {
            MBARRIER_EXPECT_TX(sb + SM_MBAR + t * 8, 65536);
            CP_BULK(sb + SM_B + t * 65536, g_cb_tiled + (size_t)t * 65536, 65536,
                    sb + SM_MBAR + t * 8);
        }
    }

    // convert z tile (128x256 fp32) to swizzled bf16 chunks (overlaps copies)
    #pragma unroll
    for (int i = 0; i < 16; i++) {
        int id  = tid + i * 512;
        int row = id >> 6;
        int col = (id & 63) * 4;
        int dc  = col >> 6;
        int cl  = col & 63;
        float4 v = *(const float4*)(z + (size_t)(qbase + row) * DD + col);
        __nv_bfloat162 h0 = {__float2bfloat16_rn(v.x), __float2bfloat16_rn(v.y)};
        __nv_bfloat162 h1 = {__float2bfloat16_rn(v.z), __float2bfloat16_rn(v.w)};
        uint2 hu = {*(uint32_t*)&h0, *(uint32_t*)&h1};
        uint32_t o = (uint32_t)(dc * 16384) + swz((uint32_t)(row * 128 + cl * 2));
        *(uint2*)(smem + SM_A + o) = hu;
    }
    __syncthreads();   // A tile visible to all warps

    const int a_r  = wm * 32 + (lane & 15);
    const int a_c8 = (lane >> 4) * 8;
    const int b_r  = wn * 32 + (lane & 7) + ((lane >> 4) & 1) * 8;
    const int b_c8 = ((lane >> 3) & 1) * 8;

    float t1d[4], t2d[4];
    int   t1i[4];
    #pragma unroll
    for (int s = 0; s < 4; s++) { t1d[s] = INFINITY; t2d[s] = INFINITY; t1i[s] = 0x7fffffff; }

    float acc[2][4][4] = {};

    #pragma unroll 1
    for (int t = 0; t < NTILES; t++) {
        const int slot = t & 1;
        const int par  = (t >> 1) & 1;
        MBARRIER_WAIT_PARITY(sb + SM_MBAR + slot * 8, par);
        const uint32_t bbase = sb + SM_B + (uint32_t)slot * 65536;

        #pragma unroll
        for (int dc = 0; dc < 4; dc++) {
            const uint32_t a_base = sb + SM_A + dc * 16384;
            const uint32_t b_base = bbase + dc * 16384;
            #pragma unroll
            for (int k16 = 0; k16 < 4; k16++) {
                const int kc = k16 * 16;
                uint32_t ah[2][4], fh[2][4];
                #pragma unroll
                for (int mt = 0; mt < 2; mt++) {
                    uint32_t o = swz((uint32_t)((a_r + mt * 16) * 128 + (a_c8 + kc) * 2));
                    LDSM_X4(ah[mt][0], ah[mt][1], ah[mt][2], ah[mt][3], a_base + o);
                }
                #pragma unroll
                for (int np = 0; np < 2; np++) {
                    uint32_t o = swz((uint32_t)((b_r + np * 16) * 128 + (b_c8 + kc) * 2));
                    LDSM_X4(fh[np][0], fh[np][1], fh[np][2], fh[np][3], b_base + o);
                }
                #pragma unroll
                for (int mt = 0; mt < 2; mt++)
                    #pragma unroll
                    for (int nt = 0; nt < 4; nt++) {
                        float* c = acc[mt][nt];
                        MMA_BF16(c[0], c[1], c[2], c[3],
                                 ah[mt][0], ah[mt][1], ah[mt][2], ah[mt][3],
                                 fh[nt >> 1][(nt & 1) * 2], fh[nt >> 1][(nt & 1) * 2 + 1]);
                    }
            }
        }

        // ---- per-tile epilogue: per-thread top-2 per row-slot ---------------
        const int nbase = t * NTILE;
        #pragma unroll
        for (int mt = 0; mt < 2; mt++)
            #pragma unroll
            for (int half = 0; half < 2; half++) {
                const int slot2 = mt * 2 + half;
                #pragma unroll
                for (int nt = 0; nt < 4; nt++) {
                    const int coll = wn * 32 + nt * 8 + (lane & 3) * 2;
                    #pragma unroll
                    for (int p = 0; p < 2; p++) {
                        float cq = __ldg(&g_cbsq[nbase + coll + p]);
                        float d  = cq - 2.0f * acc[mt][nt][half * 2 + p];
                        int gi = nbase + coll + p;
                        if (d < t1d[slot2] || (d == t1d[slot2] && gi < t1i[slot2])) {
                            t2d[slot2] = t1d[slot2]; t1d[slot2] = d; t1i[slot2] = gi;
                        } else if (d < t2d[slot2]) {
                            t2d[slot2] = d;
                        }
                    }
                }
            }
        #pragma unroll
        for (int mt = 0; mt < 2; mt++)
            #pragma unroll
            for (int nt = 0; nt < 4; nt++)
                #pragma unroll
                for (int p = 0; p < 4; p++)
                    acc[mt][nt][p] = 0.f;

        __syncthreads();   // all warps done reading this slot
        if (tid == 0 && t + 2 < NTILES) {
            MBARRIER_EXPECT_TX(sb + SM_MBAR + slot * 8, 65536);
            CP_BULK(bbase, g_cb_tiled + (size_t)(t + 2) * 65536, 65536,
                    sb + SM_MBAR + slot * 8);
        }
    }

    // ---- dump per-slot top-2 to smem (overlay on A) --------------------------
    __syncthreads();
    float* sd1 = (float*)(smem);            // [128][16]
    int*   si1 = (int*)(smem + 8192);       // [128][16]
    float* sd2 = (float*)(smem + 16384);    // [128][16]

    #pragma unroll
    for (int slot = 0; slot < 4; slot++) {
        int row  = wm * 32 + (slot >> 1) * 16 + (slot & 1) * 8 + (lane >> 2);
        int sidx = wn * 4 + (lane & 3);     // disjoint code subset per sidx
        sd1[row * 16 + sidx] = t1d[slot];
        si1[row * 16 + sidx] = t1i[slot];
        sd2[row * 16 + sidx] = t2d[slot];
    }
    __syncthreads();

    // ---- per-query triage ----------------------------------------------------
    if (tid < MT) {
        const int q = qbase + tid;
        float c1 = INFINITY; int c1i = 0x7fffffff;
        #pragma unroll
        for (int s2 = 0; s2 < 16; s2++) {
            float d = sd1[tid * 16 + s2];
            int   i = si1[tid * 16 + s2];
            if (d < c1 || (d == c1 && i < c1i)) { c1 = d; c1i = i; }
        }
        const float win = c1 + WTH;
        bool t2in = false;
        int  n = 0;
        int  cands[MAXC];
        #pragma unroll
        for (int s2 = 0; s2 < 16; s2++) {
            if (sd2[tid * 16 + s2] < win) t2in = true;
            float d = sd1[tid * 16 + s2];
            if (d < win) {
                if (n < MAXC) cands[n] = si1[tid * 16 + s2];
                n++;
            }
        }
        out[q] = (float)c1i;
        if (t2in || n > MAXC) {
            int pos = atomicAdd(&g_cntB, 1);
            g_listB[pos] = q;
        } else if (n > 1) {
            #pragma unroll
            for (int j = 0; j < MAXC; j++)
                if (j < n) g_cands[q * MAXC + j] = cands[j];
            g_ncand[q] = n;
            int pos = atomicAdd(&g_cntA, 1);
            g_listA[pos] = q;
        }
    }
}

// ---------------------------------------------------------------------------
// Recheck A: exact fp32 distance over stored candidates (warp per query).
// ---------------------------------------------------------------------------
__global__ void recheckA_kernel(const float* __restrict__ z,
                                const float* __restrict__ cb,
                                float* __restrict__ out) {
    const int gw    = (blockIdx.x * blockDim.x + threadIdx.x) >> 5;
    const int lane  = threadIdx.x & 31;
    const int nwarp = (gridDim.x * blockDim.x) >> 5;

    const int count = g_cntA;
    for (int it = gw; it < count; it += nwarp) {
        const int q = g_listA[it];
        const int n = g_ncand[q];

        float zr[8];
        #pragma unroll
        for (int i = 0; i < 8; i++) zr[i] = z[(size_t)q * DD + lane + i * 32];

        float bd = INFINITY;
        int   bi = 0x7fffffff;
        for (int j = 0; j < n; j++) {
            int idx = g_cands[q * MAXC + j];
            const float* cr = cb + (size_t)idx * DD;
            float dot = 0.f;
            #pragma unroll
            for (int i = 0; i < 8; i++) dot = fmaf(zr[i], cr[lane + i * 32], dot);
            #pragma unroll
            for (int off = 16; off; off >>= 1) dot += __shfl_xor_sync(0xffffffffu, dot, off);
            float dist = g_cbsq[idx] - 2.0f * dot;
            if (dist < bd || (dist == bd && idx < bi)) { bd = dist; bi = idx; }
        }
        if (lane == 0) out[q] = (float)bi;
    }
}

// ---------------------------------------------------------------------------
// Fallback B: exact fp32 full scan (rare). 256-thr block strides the list.
// ---------------------------------------------------------------------------
__global__ void fallbackB_kernel(const float* __restrict__ z,
                                 const float* __restrict__ cb,
                                 float* __restrict__ out) {
    const int tid  = threadIdx.x;
    const int wid  = tid >> 5;
    const int lane = tid & 31;
    __shared__ float swd[8];
    __shared__ int   swi[8];

    const int count = g_cntB;
    for (int it = blockIdx.x; it < count; it += gridDim.x) {
        const int q = g_listB[it];

        float zr[8];
        #pragma unroll
        for (int i = 0; i < 8; i++) zr[i] = z[(size_t)q * DD + lane + i * 32];

        float bd = INFINITY;
        int   bi = 0x7fffffff;
        const int n0 = wid * (KC / 8);
        #pragma unroll 2
        for (int k = 0; k < KC / 8; k++) {
            const int n = n0 + k;
            const float* cr = cb + (size_t)n * DD;
            float dot = 0.f;
            #pragma unroll
            for (int i = 0; i < 8; i++) dot = fmaf(zr[i], cr[lane + i * 32], dot);
            #pragma unroll
            for (int off = 16; off; off >>= 1) dot += __shfl_xor_sync(0xffffffffu, dot, off);
            float dist = g_cbsq[n] - 2.0f * dot;
            if (dist < bd) { bd = dist; bi = n; }
        }
        if (lane == 0) { swd[wid] = bd; swi[wid] = bi; }
        __syncthreads();
        if (tid == 0) {
            float d = swd[0]; int i1 = swi[0];
            #pragma unroll
            for (int w = 1; w < 8; w++) {
                if (swd[w] < d || (swd[w] == d && swi[w] < i1)) { d = swd[w]; i1 = swi[w]; }
            }
            out[q] = (float)i1;
        }
        __syncthreads();
    }
}

// ---------------------------------------------------------------------------
extern "C" void kernel_launch(void* const* d_in, const int* in_sizes, int n_in,
                              void* d_out, int out_size) {
    // z_e_x is always the larger buffer (4x codebook).
    const float* z;
    const float* cb;
    if (in_sizes[0] >= in_sizes[1]) { z = (const float*)d_in[0]; cb = (const float*)d_in[1]; }
    else                            { cb = (const float*)d_in[0]; z = (const float*)d_in[1]; }
    float* out = (float*)d_out;

    cudaFuncSetAttribute(vq_mma_kernel,
                         cudaFuncAttributeMaxDynamicSharedMemorySize, SM_TOTAL);

    prep_kernel<<<KC / 8, 256>>>(cb);
    vq_mma_kernel<<<NQ / MT, 512, SM_TOTAL>>>(z, out);
    recheckA_kernel<<<1024, 256>>>(z, cb, out);
    fallbackB_kernel<<<256, 256>>>(z, cb, out);
}

// round 13
// speedup vs baseline: 1.3576x; 1.3576x over previous
#include <cuda_runtime.h>
#include <cuda_bf16.h>
#include <cstdint>
#include <math.h>

#define NQ      32768
#define KC      8192
#define DD      256
#define MT      64            // queries per CTA
#define NTILE   128           // codes per tile
#define NTILES  (KC / NTILE)  // 64
#define NSTAGES (NTILES * 4)  // 256 (64-dim chunks)
#define WTH     1.0e-4f       // coarse trust window (>= 2x worst coarse error)
#define MAXC    8             // max stored candidates per query

// ---------------- device scratch (no cudaMalloc) ----------------------------
__device__ float         g_cbsq[KC];
__device__ __nv_bfloat16 g_cb_hi[KC * DD];
__device__ int           g_listA[NQ];
__device__ int           g_cntA;
__device__ int           g_listB[NQ];
__device__ int           g_cntB;
__device__ int           g_cands[NQ * MAXC];
__device__ int           g_ncand[NQ];

// ---------------- smem layout (bytes) ---------------------------------------
// A: 4 dc-chunks x (64 x 64 bf16 SW128, 8KB) = 32KB
// B: 3 stages x 16KB = 48KB; triage overlays A after mainloop (12KB needed)
#define SM_A     0
#define SM_B     32768
#define SM_TOTAL 81920         // 80 KB -> 2 CTAs/SM

__device__ __forceinline__ uint32_t smem_u32(const void* p) {
    uint32_t a;
    asm("{ .reg .u64 t; cvta.to.shared.u64 t, %1; cvt.u32.u64 %0, t; }"
        : "=r"(a) : "l"(p));
    return a;
}
__device__ __forceinline__ uint32_t swz(uint32_t b) { return b ^ ((b >> 3) & 0x70); }

#define LDSM_X4(r0, r1, r2, r3, addr) \
    asm volatile("ldmatrix.sync.aligned.m8n8.x4.shared.b16 {%0,%1,%2,%3}, [%4];" \
                 : "=r"(r0), "=r"(r1), "=r"(r2), "=r"(r3) : "r"(addr))

#define MMA_BF16(c0, c1, c2, c3, a0, a1, a2, a3, b0, b1) \
    asm volatile("mma.sync.aligned.m16n8k16.row.col.f32.bf16.bf16.f32 " \
                 "{%0,%1,%2,%3}, {%4,%5,%6,%7}, {%8,%9}, {%0,%1,%2,%3};" \
                 : "+f"(c0), "+f"(c1), "+f"(c2), "+f"(c3) \
                 : "r"(a0), "r"(a1), "r"(a2), "r"(a3), "r"(b0), "r"(b1))

#define CP16(dst, src) \
    asm volatile("cp.async.cg.shared.global [%0], [%1], 16;" :: "r"(dst), "l"(src))
#define CP_COMMIT() asm volatile("cp.async.commit_group;" ::: "memory")
#define CP_WAIT(n)  asm volatile("cp.async.wait_group %0;" :: "n"(n) : "memory")

// ---------------------------------------------------------------------------
// Prep: codebook -> bf16 + ||e||^2; zero list counters. One warp per code.
// ---------------------------------------------------------------------------
__global__ void prep_kernel(const float* __restrict__ cb) {
    if (blockIdx.x == 0 && threadIdx.x == 0) { g_cntA = 0; g_cntB = 0; }
    int w = (blockIdx.x * blockDim.x + threadIdx.x) >> 5;
    int lane = threadIdx.x & 31;
    if (w >= KC) return;
    const float4* row = (const float4*)(cb + (size_t)w * DD);
    float s = 0.f;
    #pragma unroll
    for (int i = 0; i < 2; i++) {
        int f = lane + i * 32;
        float4 v = row[f];
        s += v.x * v.x + v.y * v.y + v.z * v.z + v.w * v.w;
        __nv_bfloat162 h0 = {__float2bfloat16_rn(v.x), __float2bfloat16_rn(v.y)};
        __nv_bfloat162 h1 = {__float2bfloat16_rn(v.z), __float2bfloat16_rn(v.w)};
        uint2 hu = {*(uint32_t*)&h0, *(uint32_t*)&h1};
        *(uint2*)(g_cb_hi + (size_t)w * DD + f * 4) = hu;
    }
    #pragma unroll
    for (int off = 16; off; off >>= 1) s += __shfl_xor_sync(0xffffffffu, s, off);
    if (lane == 0) g_cbsq[w] = s;
}

// ---------------------------------------------------------------------------
// Main: single-pass bf16 HMMA + per-slot top-2 + window triage.
// 512 threads = 16 warps (4M x 4N), warp tile 16M x 32N. CTA: 64 q x 8192 c.
// 80KB smem -> 2 CTAs/SM (32 warps/SM) for latency hiding.
// ---------------------------------------------------------------------------
__global__ void __launch_bounds__(512, 2)
vq_mma_kernel(const float* __restrict__ z, float* __restrict__ out) {
    extern __shared__ char smem[];
    const uint32_t sb = smem_u32(smem);
    const int tid  = threadIdx.x;
    const int wid  = tid >> 5;
    const int lane = tid & 31;
    const int wm   = wid >> 2;     // 0..3 -> 16 query rows each
    const int wn   = wid & 3;      // 0..3 -> 32 code cols each
    const int qbase = blockIdx.x * MT;

    const int cp_row0 = tid >> 3;            // 0..63
    const int cp_row1 = (tid + 512) >> 3;    // 64..127
    const int cp_c8   = (tid & 7) * 8;
    const uint32_t cp_o0 = swz((uint32_t)(cp_row0 * 128 + cp_c8 * 2));
    const uint32_t cp_o1 = swz((uint32_t)(cp_row1 * 128 + cp_c8 * 2));

    // prologue: issue B stages 0,1
    #pragma unroll
    for (int s = 0; s < 2; s++) {
        const uint32_t bst = sb + SM_B + s * 16384;
        const int tile = s >> 2, dc = s & 3;
        size_t src0 = (size_t)(tile * NTILE + cp_row0) * DD + dc * 64 + cp_c8;
        size_t src1 = (size_t)(tile * NTILE + cp_row1) * DD + dc * 64 + cp_c8;
        CP16(bst + cp_o0, g_cb_hi + src0);
        CP16(bst + cp_o1, g_cb_hi + src1);
        CP_COMMIT();
    }

    // convert z tile (64x256 fp32) to swizzled bf16 chunks (8 float4/thread)
    #pragma unroll
    for (int i = 0; i < 8; i++) {
        int id  = tid + i * 512;           // float4 id, 4096 total
        int row = id >> 6;                 // 0..63
        int col = (id & 63) * 4;
        int dc  = col >> 6;
        int cl  = col & 63;
        float4 v = *(const float4*)(z + (size_t)(qbase + row) * DD + col);
        __nv_bfloat162 h0 = {__float2bfloat16_rn(v.x), __float2bfloat16_rn(v.y)};
        __nv_bfloat162 h1 = {__float2bfloat16_rn(v.z), __float2bfloat16_rn(v.w)};
        uint2 hu = {*(uint32_t*)&h0, *(uint32_t*)&h1};
        uint32_t o = (uint32_t)(dc * 8192) + swz((uint32_t)(row * 128 + cl * 2));
        *(uint2*)(smem + SM_A + o) = hu;
    }

    const int a_r  = wm * 16 + (lane & 15);
    const int a_c8 = (lane >> 4) * 8;
    const int b_r  = wn * 32 + (lane & 7) + ((lane >> 4) & 1) * 8;
    const int b_c8 = ((lane >> 3) & 1) * 8;

    // per-thread top-2 per row-slot (2 slots: frag rows lane>>2 and +8)
    float t1d[2], t2d[2];
    int   t1i[2];
    #pragma unroll
    for (int s = 0; s < 2; s++) { t1d[s] = INFINITY; t2d[s] = INFINITY; t1i[s] = 0x7fffffff; }

    float acc[4][4] = {};

    #pragma unroll 1
    for (int s = 0; s < NSTAGES; s++) {
        const int tile = s >> 2;
        const int dc   = s & 3;
        const uint32_t buf = sb + SM_B + (uint32_t)(s % 3) * 16384;

        if (s + 1 < NSTAGES) { CP_WAIT(1); } else { CP_WAIT(0); }
        __syncthreads();

        if (s + 2 < NSTAGES) {
            const int nt_ = (s + 2) >> 2, ndc = (s + 2) & 3;
            const uint32_t bst = sb + SM_B + (uint32_t)((s + 2) % 3) * 16384;
            size_t src0 = (size_t)(nt_ * NTILE + cp_row0) * DD + ndc * 64 + cp_c8;
            size_t src1 = (size_t)(nt_ * NTILE + cp_row1) * DD + ndc * 64 + cp_c8;
            CP16(bst + cp_o0, g_cb_hi + src0);
            CP16(bst + cp_o1, g_cb_hi + src1);
            CP_COMMIT();
        }

        const uint32_t a_base = sb + SM_A + dc * 8192;

        #pragma unroll
        for (int k16 = 0; k16 < 4; k16++) {
            const int kc = k16 * 16;
            uint32_t ah[4], fh[2][4];
            {
                uint32_t o = swz((uint32_t)(a_r * 128 + (a_c8 + kc) * 2));
                LDSM_X4(ah[0], ah[1], ah[2], ah[3], a_base + o);
            }
            #pragma unroll
            for (int np = 0; np < 2; np++) {
                uint32_t o = swz((uint32_t)((b_r + np * 16) * 128 + (b_c8 + kc) * 2));
                LDSM_X4(fh[np][0], fh[np][1], fh[np][2], fh[np][3], buf + o);
            }
            #pragma unroll
            for (int nt = 0; nt < 4; nt++) {
                float* c = acc[nt];
                MMA_BF16(c[0], c[1], c[2], c[3],
                         ah[0], ah[1], ah[2], ah[3],
                         fh[nt >> 1][(nt & 1) * 2], fh[nt >> 1][(nt & 1) * 2 + 1]);
            }
        }

        // ---- epilogue on tile boundary: per-thread top-2 per row-slot ------
        if (dc == 3) {
            const int nbase = tile * NTILE;
            #pragma unroll
            for (int half = 0; half < 2; half++) {
                #pragma unroll
                for (int nt = 0; nt < 4; nt++) {
                    const int coll = wn * 32 + nt * 8 + (lane & 3) * 2;
                    #pragma unroll
                    for (int p = 0; p < 2; p++) {
                        float cq = __ldg(&g_cbsq[nbase + coll + p]);
                        float d  = cq - 2.0f * acc[nt][half * 2 + p];
                        int gi = nbase + coll + p;
                        if (d < t1d[half] || (d == t1d[half] && gi < t1i[half])) {
                            t2d[half] = t1d[half]; t1d[half] = d; t1i[half] = gi;
                        } else if (d < t2d[half]) {
                            t2d[half] = d;
                        }
                    }
                }
            }
            #pragma unroll
            for (int nt = 0; nt < 4; nt++)
                #pragma unroll
                for (int p = 0; p < 4; p++)
                    acc[nt][p] = 0.f;
        }
    }

    // ---- dump per-slot top-2 to smem (overlay on A) --------------------------
    __syncthreads();
    float* sd1 = (float*)(smem);            // [64][16]
    int*   si1 = (int*)(smem + 4096);       // [64][16]
    float* sd2 = (float*)(smem + 8192);     // [64][16]

    #pragma unroll
    for (int half = 0; half < 2; half++) {
        int row  = wm * 16 + half * 8 + (lane >> 2);
        int sidx = wn * 4 + (lane & 3);     // disjoint code subset per sidx
        sd1[row * 16 + sidx] = t1d[half];
        si1[row * 16 + sidx] = t1i[half];
        sd2[row * 16 + sidx] = t2d[half];
    }
    __syncthreads();

    // ---- per-query triage ----------------------------------------------------
    if (tid < MT) {
        const int q = qbase + tid;
        float c1 = INFINITY; int c1i = 0x7fffffff;
        #pragma unroll
        for (int s2 = 0; s2 < 16; s2++) {
            float d = sd1[tid * 16 + s2];
            int   i = si1[tid * 16 + s2];
            if (d < c1 || (d == c1 && i < c1i)) { c1 = d; c1i = i; }
        }
        const float win = c1 + WTH;
        bool t2in = false;
        int  n = 0;
        int  cands[MAXC];
        #pragma unroll
        for (int s2 = 0; s2 < 16; s2++) {
            if (sd2[tid * 16 + s2] < win) t2in = true;
            float d = sd1[tid * 16 + s2];
            if (d < win) {
                if (n < MAXC) cands[n] = si1[tid * 16 + s2];
                n++;
            }
        }
        out[q] = (float)c1i;
        if (t2in || n > MAXC) {
            int pos = atomicAdd(&g_cntB, 1);
            g_listB[pos] = q;
        } else if (n > 1) {
            #pragma unroll
            for (int j = 0; j < MAXC; j++)
                if (j < n) g_cands[q * MAXC + j] = cands[j];
            g_ncand[q] = n;
            int pos = atomicAdd(&g_cntA, 1);
            g_listA[pos] = q;
        }
    }
}

// ---------------------------------------------------------------------------
// Recheck A: exact fp32 distance over stored candidates (warp per query).
// ---------------------------------------------------------------------------
__global__ void recheckA_kernel(const float* __restrict__ z,
                                const float* __restrict__ cb,
                                float* __restrict__ out) {
    const int gw    = (blockIdx.x * blockDim.x + threadIdx.x) >> 5;
    const int lane  = threadIdx.x & 31;
    const int nwarp = (gridDim.x * blockDim.x) >> 5;

    const int count = g_cntA;
    for (int it = gw; it < count; it += nwarp) {
        const int q = g_listA[it];
        const int n = g_ncand[q];

        float zr[8];
        #pragma unroll
        for (int i = 0; i < 8; i++) zr[i] = z[(size_t)q * DD + lane + i * 32];

        float bd = INFINITY;
        int   bi = 0x7fffffff;
        for (int j = 0; j < n; j++) {
            int idx = g_cands[q * MAXC + j];
            const float* cr = cb + (size_t)idx * DD;
            float dot = 0.f;
            #pragma unroll
            for (int i = 0; i < 8; i++) dot = fmaf(zr[i], cr[lane + i * 32], dot);
            #pragma unroll
            for (int off = 16; off; off >>= 1) dot += __shfl_xor_sync(0xffffffffu, dot, off);
            float dist = g_cbsq[idx] - 2.0f * dot;
            if (dist < bd || (dist == bd && idx < bi)) { bd = dist; bi = idx; }
        }
        if (lane == 0) out[q] = (float)bi;
    }
}

// ---------------------------------------------------------------------------
// Fallback B: exact fp32 full scan (rare). 256-thr block strides the list.
// ---------------------------------------------------------------------------
__global__ void fallbackB_kernel(const float* __restrict__ z,
                                 const float* __restrict__ cb,
                                 float* __restrict__ out) {
    const int tid  = threadIdx.x;
    const int wid  = tid >> 5;
    const int lane = tid & 31;
    __shared__ float swd[8];
    __shared__ int   swi[8];

    const int count = g_cntB;
    for (int it = blockIdx.x; it < count; it += gridDim.x) {
        const int q = g_listB[it];

        float zr[8];
        #pragma unroll
        for (int i = 0; i < 8; i++) zr[i] = z[(size_t)q * DD + lane + i * 32];

        float bd = INFINITY;
        int   bi = 0x7fffffff;
        const int n0 = wid * (KC / 8);
        #pragma unroll 2
        for (int k = 0; k < KC / 8; k++) {
            const int n = n0 + k;
            const float* cr = cb + (size_t)n * DD;
            float dot = 0.f;
            #pragma unroll
            for (int i = 0; i < 8; i++) dot = fmaf(zr[i], cr[lane + i * 32], dot);
            #pragma unroll
            for (int off = 16; off; off >>= 1) dot += __shfl_xor_sync(0xffffffffu, dot, off);
            float dist = g_cbsq[n] - 2.0f * dot;
            if (dist < bd) { bd = dist; bi = n; }
        }
        if (lane == 0) { swd[wid] = bd; swi[wid] = bi; }
        __syncthreads();
        if (tid == 0) {
            float d = swd[0]; int i1 = swi[0];
            #pragma unroll
            for (int w = 1; w < 8; w++) {
                if (swd[w] < d || (swd[w] == d && swi[w] < i1)) { d = swd[w]; i1 = swi[w]; }
            }
            out[q] = (float)i1;
        }
        __syncthreads();
    }
}

// ---------------------------------------------------------------------------
extern "C" void kernel_launch(void* const* d_in, const int* in_sizes, int n_in,
                              void* d_out, int out_size) {
    // z_e_x is always the larger buffer (4x codebook).
    const float* z;
    const float* cb;
    if (in_sizes[0] >= in_sizes[1]) { z = (const float*)d_in[0]; cb = (const float*)d_in[1]; }
    else                            { cb = (const float*)d_in[0]; z = (const float*)d_in[1]; }
    float* out = (float*)d_out;

    cudaFuncSetAttribute(vq_mma_kernel,
                         cudaFuncAttributeMaxDynamicSharedMemorySize, SM_TOTAL);

    prep_kernel<<<KC / 8, 256>>>(cb);
    vq_mma_kernel<<<NQ / MT, 512, SM_TOTAL>>>(z, out);
    recheckA_kernel<<<1024, 256>>>(z, cb, out);
    fallbackB_kernel<<<256, 256>>>(z, cb, out);
}

// round 14
// speedup vs baseline: 1.4191x; 1.0453x over previous
#include <cuda_runtime.h>
#include <cuda_bf16.h>
#include <cstdint>
#include <math.h>

#define NQ      32768
#define KC      8192
#define DD      256
#define MT      256           // queries per CTA
#define NTILE   128           // codes per tile
#define NTILES  (KC / NTILE)  // 64
#define NSTAGES (NTILES * 4)  // 256 (64-dim chunks)
#define WTH     1.0e-4f       // coarse trust window (>= 2x worst coarse error)
#define MAXC    8             // max stored candidates per query

// ---------------- device scratch (no cudaMalloc) ----------------------------
__device__ float         g_cbsq[KC];
__device__ __nv_bfloat16 g_cb_hi[KC * DD];
__device__ int           g_listA[NQ];
__device__ int           g_cntA;
__device__ int           g_listB[NQ];
__device__ int           g_cntB;
__device__ int           g_cands[NQ * MAXC];
__device__ int           g_ncand[NQ];

// ---------------- smem layout (bytes) ---------------------------------------
// A: 4 dc-chunks x (256 x 64 bf16 SW128, 32KB) = 128KB
// B: 3 stages x 16KB = 48KB ; triage overlays A after the mainloop (48KB)
#define SM_A     0
#define SM_B     131072
#define SM_TOTAL 180224        // 176 KB -> 1 CTA/SM

__device__ __forceinline__ uint32_t smem_u32(const void* p) {
    uint32_t a;
    asm("{ .reg .u64 t; cvta.to.shared.u64 t, %1; cvt.u32.u64 %0, t; }"
        : "=r"(a) : "l"(p));
    return a;
}
__device__ __forceinline__ uint32_t swz(uint32_t b) { return b ^ ((b >> 3) & 0x70); }

#define LDSM_X4(r0, r1, r2, r3, addr) \
    asm volatile("ldmatrix.sync.aligned.m8n8.x4.shared.b16 {%0,%1,%2,%3}, [%4];" \
                 : "=r"(r0), "=r"(r1), "=r"(r2), "=r"(r3) : "r"(addr))

#define MMA_BF16(c0, c1, c2, c3, a0, a1, a2, a3, b0, b1) \
    asm volatile("mma.sync.aligned.m16n8k16.row.col.f32.bf16.bf16.f32 " \
                 "{%0,%1,%2,%3}, {%4,%5,%6,%7}, {%8,%9}, {%0,%1,%2,%3};" \
                 : "+f"(c0), "+f"(c1), "+f"(c2), "+f"(c3) \
                 : "r"(a0), "r"(a1), "r"(a2), "r"(a3), "r"(b0), "r"(b1))

#define CP16(dst, src) \
    asm volatile("cp.async.cg.shared.global [%0], [%1], 16;" :: "r"(dst), "l"(src))
#define CP_COMMIT() asm volatile("cp.async.commit_group;" ::: "memory")
#define CP_WAIT(n)  asm volatile("cp.async.wait_group %0;" :: "n"(n) : "memory")

// ---------------------------------------------------------------------------
// Prep: codebook -> bf16 + ||e||^2; zero list counters. One warp per code.
// ---------------------------------------------------------------------------
__global__ void prep_kernel(const float* __restrict__ cb) {
    if (blockIdx.x == 0 && threadIdx.x == 0) { g_cntA = 0; g_cntB = 0; }
    int w = (blockIdx.x * blockDim.x + threadIdx.x) >> 5;
    int lane = threadIdx.x & 31;
    if (w >= KC) return;
    const float4* row = (const float4*)(cb + (size_t)w * DD);
    float s = 0.f;
    #pragma unroll
    for (int i = 0; i < 2; i++) {
        int f = lane + i * 32;
        float4 v = row[f];
        s += v.x * v.x + v.y * v.y + v.z * v.z + v.w * v.w;
        __nv_bfloat162 h0 = {__float2bfloat16_rn(v.x), __float2bfloat16_rn(v.y)};
        __nv_bfloat162 h1 = {__float2bfloat16_rn(v.z), __float2bfloat16_rn(v.w)};
        uint2 hu = {*(uint32_t*)&h0, *(uint32_t*)&h1};
        *(uint2*)(g_cb_hi + (size_t)w * DD + f * 4) = hu;
    }
    #pragma unroll
    for (int off = 16; off; off >>= 1) s += __shfl_xor_sync(0xffffffffu, s, off);
    if (lane == 0) g_cbsq[w] = s;
}

// ---------------------------------------------------------------------------
// Main: single-pass bf16 HMMA + per-slot top-2 + window triage.
// 1024 threads = 32 warps (8M x 4N), warp tile 32M x 32N.
// CTA: 256 queries x all 8192 codes. 128 CTAs = one wave.
// ---------------------------------------------------------------------------
__global__ void __launch_bounds__(1024, 1)
vq_mma_kernel(const float* __restrict__ z, float* __restrict__ out) {
    extern __shared__ char smem[];
    const uint32_t sb = smem_u32(smem);
    const int tid  = threadIdx.x;
    const int wid  = tid >> 5;
    const int lane = tid & 31;
    const int wm   = wid >> 2;     // 0..7 -> 32 query rows each
    const int wn   = wid & 3;      // 0..3 -> 32 code cols each
    const int qbase = blockIdx.x * MT;

    // cp.async: 1024 chunks of 16B per 16KB stage, one per thread
    const int cp_row = tid >> 3;             // 0..127
    const int cp_c8  = (tid & 7) * 8;
    const uint32_t cp_o = swz((uint32_t)(cp_row * 128 + cp_c8 * 2));

    // prologue: issue B stages 0,1
    #pragma unroll
    for (int s = 0; s < 2; s++) {
        const uint32_t bst = sb + SM_B + s * 16384;
        const int tile = s >> 2, dc = s & 3;
        size_t src = (size_t)(tile * NTILE + cp_row) * DD + dc * 64 + cp_c8;
        CP16(bst + cp_o, g_cb_hi + src);
        CP_COMMIT();
    }

    // convert z tile (256x256 fp32) to swizzled bf16 chunks (16 float4/thread)
    #pragma unroll
    for (int i = 0; i < 16; i++) {
        int id  = tid + i * 1024;          // float4 id, 16384 total
        int row = id >> 6;                 // 0..255
        int col = (id & 63) * 4;
        int dc  = col >> 6;
        int cl  = col & 63;
        float4 v = *(const float4*)(z + (size_t)(qbase + row) * DD + col);
        __nv_bfloat162 h0 = {__float2bfloat16_rn(v.x), __float2bfloat16_rn(v.y)};
        __nv_bfloat162 h1 = {__float2bfloat16_rn(v.z), __float2bfloat16_rn(v.w)};
        uint2 hu = {*(uint32_t*)&h0, *(uint32_t*)&h1};
        uint32_t o = (uint32_t)(dc * 32768) + swz((uint32_t)(row * 128 + cl * 2));
        *(uint2*)(smem + SM_A + o) = hu;
    }

    const int a_r  = wm * 32 + (lane & 15);
    const int a_c8 = (lane >> 4) * 8;
    const int b_r  = wn * 32 + (lane & 7) + ((lane >> 4) & 1) * 8;
    const int b_c8 = ((lane >> 3) & 1) * 8;

    // per-thread top-2 per row-slot (4 slots: mt*2+half)
    float t1d[4], t2d[4];
    int   t1i[4];
    #pragma unroll
    for (int s = 0; s < 4; s++) { t1d[s] = INFINITY; t2d[s] = INFINITY; t1i[s] = 0x7fffffff; }

    float acc[2][4][4] = {};

    #pragma unroll 1
    for (int s = 0; s < NSTAGES; s++) {
        const int tile = s >> 2;
        const int dc   = s & 3;
        const uint32_t buf = sb + SM_B + (uint32_t)(s % 3) * 16384;

        if (s + 1 < NSTAGES) { CP_WAIT(1); } else { CP_WAIT(0); }
        __syncthreads();

        if (s + 2 < NSTAGES) {
            const int nt_ = (s + 2) >> 2, ndc = (s + 2) & 3;
            const uint32_t bst = sb + SM_B + (uint32_t)((s + 2) % 3) * 16384;
            size_t src = (size_t)(nt_ * NTILE + cp_row) * DD + ndc * 64 + cp_c8;
            CP16(bst + cp_o, g_cb_hi + src);
            CP_COMMIT();
        }

        const uint32_t a_base = sb + SM_A + dc * 32768;

        #pragma unroll
        for (int k16 = 0; k16 < 4; k16++) {
            const int kc = k16 * 16;
            uint32_t ah[2][4], fh[2][4];
            #pragma unroll
            for (int mt = 0; mt < 2; mt++) {
                uint32_t o = swz((uint32_t)((a_r + mt * 16) * 128 + (a_c8 + kc) * 2));
                LDSM_X4(ah[mt][0], ah[mt][1], ah[mt][2], ah[mt][3], a_base + o);
            }
            #pragma unroll
            for (int np = 0; np < 2; np++) {
                uint32_t o = swz((uint32_t)((b_r + np * 16) * 128 + (b_c8 + kc) * 2));
                LDSM_X4(fh[np][0], fh[np][1], fh[np][2], fh[np][3], buf + o);
            }
            #pragma unroll
            for (int mt = 0; mt < 2; mt++)
                #pragma unroll
                for (int nt = 0; nt < 4; nt++) {
                    float* c = acc[mt][nt];
                    MMA_BF16(c[0], c[1], c[2], c[3],
                             ah[mt][0], ah[mt][1], ah[mt][2], ah[mt][3],
                             fh[nt >> 1][(nt & 1) * 2], fh[nt >> 1][(nt & 1) * 2 + 1]);
                }
        }

        // ---- epilogue on tile boundary: per-thread top-2 per row-slot ------
        if (dc == 3) {
            const int nbase = tile * NTILE;
            #pragma unroll
            for (int mt = 0; mt < 2; mt++)
                #pragma unroll
                for (int half = 0; half < 2; half++) {
                    const int slot = mt * 2 + half;
                    #pragma unroll
                    for (int nt = 0; nt < 4; nt++) {
                        const int coll = wn * 32 + nt * 8 + (lane & 3) * 2;
                        #pragma unroll
                        for (int p = 0; p < 2; p++) {
                            float cq = __ldg(&g_cbsq[nbase + coll + p]);
                            float d  = cq - 2.0f * acc[mt][nt][half * 2 + p];
                            int gi = nbase + coll + p;
                            if (d < t1d[slot] || (d == t1d[slot] && gi < t1i[slot])) {
                                t2d[slot] = t1d[slot]; t1d[slot] = d; t1i[slot] = gi;
                            } else if (d < t2d[slot]) {
                                t2d[slot] = d;
                            }
                        }
                    }
                }
            #pragma unroll
            for (int mt = 0; mt < 2; mt++)
                #pragma unroll
                for (int nt = 0; nt < 4; nt++)
                    #pragma unroll
                    for (int p = 0; p < 4; p++)
                        acc[mt][nt][p] = 0.f;
        }
    }

    // ---- dump per-slot top-2 to smem (overlay on A) --------------------------
    __syncthreads();
    float* sd1 = (float*)(smem);            // [256][16]
    int*   si1 = (int*)(smem + 16384);      // [256][16]
    float* sd2 = (float*)(smem + 32768);    // [256][16]

    #pragma unroll
    for (int mt = 0; mt < 2; mt++)
        #pragma unroll
        for (int half = 0; half < 2; half++) {
            int slot = mt * 2 + half;
            int row  = wm * 32 + mt * 16 + half * 8 + (lane >> 2);
            int sidx = wn * 4 + (lane & 3);  // disjoint code subset per sidx
            sd1[row * 16 + sidx] = t1d[slot];
            si1[row * 16 + sidx] = t1i[slot];
            sd2[row * 16 + sidx] = t2d[slot];
        }
    __syncthreads();

    // ---- per-query triage ----------------------------------------------------
    if (tid < MT) {
        const int q = qbase + tid;
        float c1 = INFINITY; int c1i = 0x7fffffff;
        #pragma unroll
        for (int s2 = 0; s2 < 16; s2++) {
            float d = sd1[tid * 16 + s2];
            int   i = si1[tid * 16 + s2];
            if (d < c1 || (d == c1 && i < c1i)) { c1 = d; c1i = i; }
        }
        const float win = c1 + WTH;
        bool t2in = false;
        int  n = 0;
        int  cands[MAXC];
        #pragma unroll
        for (int s2 = 0; s2 < 16; s2++) {
            if (sd2[tid * 16 + s2] < win) t2in = true;
            float d = sd1[tid * 16 + s2];
            if (d < win) {
                if (n < MAXC) cands[n] = si1[tid * 16 + s2];
                n++;
            }
        }
        out[q] = (float)c1i;
        if (t2in || n > MAXC) {
            int pos = atomicAdd(&g_cntB, 1);
            g_listB[pos] = q;
        } else if (n > 1) {
            #pragma unroll
            for (int j = 0; j < MAXC; j++)
                if (j < n) g_cands[q * MAXC + j] = cands[j];
            g_ncand[q] = n;
            int pos = atomicAdd(&g_cntA, 1);
            g_listA[pos] = q;
        }
    }
}

// ---------------------------------------------------------------------------
// Recheck A: exact fp32 distance over stored candidates (warp per query).
// ---------------------------------------------------------------------------
__global__ void recheckA_kernel(const float* __restrict__ z,
                                const float* __restrict__ cb,
                                float* __restrict__ out) {
    const int gw    = (blockIdx.x * blockDim.x + threadIdx.x) >> 5;
    const int lane  = threadIdx.x & 31;
    const int nwarp = (gridDim.x * blockDim.x) >> 5;

    const int count = g_cntA;
    for (int it = gw; it < count; it += nwarp) {
        const int q = g_listA[it];
        const int n = g_ncand[q];

        float zr[8];
        #pragma unroll
        for (int i = 0; i < 8; i++) zr[i] = z[(size_t)q * DD + lane + i * 32];

        float bd = INFINITY;
        int   bi = 0x7fffffff;
        for (int j = 0; j < n; j++) {
            int idx = g_cands[q * MAXC + j];
            const float* cr = cb + (size_t)idx * DD;
            float dot = 0.f;
            #pragma unroll
            for (int i = 0; i < 8; i++) dot = fmaf(zr[i], cr[lane + i * 32], dot);
            #pragma unroll
            for (int off = 16; off; off >>= 1) dot += __shfl_xor_sync(0xffffffffu, dot, off);
            float dist = g_cbsq[idx] - 2.0f * dot;
            if (dist < bd || (dist == bd && idx < bi)) { bd = dist; bi = idx; }
        }
        if (lane == 0) out[q] = (float)bi;
    }
}

// ---------------------------------------------------------------------------
// Fallback B: exact fp32 full scan (rare). 256-thr block strides the list.
// ---------------------------------------------------------------------------
__global__ void fallbackB_kernel(const float* __restrict__ z,
                                 const float* __restrict__ cb,
                                 float* __restrict__ out) {
    const int tid  = threadIdx.x;
    const int wid  = tid >> 5;
    const int lane = tid & 31;
    __shared__ float swd[8];
    __shared__ int   swi[8];

    const int count = g_cntB;
    for (int it = blockIdx.x; it < count; it += gridDim.x) {
        const int q = g_listB[it];

        float zr[8];
        #pragma unroll
        for (int i = 0; i < 8; i++) zr[i] = z[(size_t)q * DD + lane + i * 32];

        float bd = INFINITY;
        int   bi = 0x7fffffff;
        const int n0 = wid * (KC / 8);
        #pragma unroll 2
        for (int k = 0; k < KC / 8; k++) {
            const int n = n0 + k;
            const float* cr = cb + (size_t)n * DD;
            float dot = 0.f;
            #pragma unroll
            for (int i = 0; i < 8; i++) dot = fmaf(zr[i], cr[lane + i * 32], dot);
            #pragma unroll
            for (int off = 16; off; off >>= 1) dot += __shfl_xor_sync(0xffffffffu, dot, off);
            float dist = g_cbsq[n] - 2.0f * dot;
            if (dist < bd) { bd = dist; bi = n; }
        }
        if (lane == 0) { swd[wid] = bd; swi[wid] = bi; }
        __syncthreads();
        if (tid == 0) {
            float d = swd[0]; int i1 = swi[0];
            #pragma unroll
            for (int w = 1; w < 8; w++) {
                if (swd[w] < d || (swd[w] == d && swi[w] < i1)) { d = swd[w]; i1 = swi[w]; }
            }
            out[q] = (float)i1;
        }
        __syncthreads();
    }
}

// ---------------------------------------------------------------------------
extern "C" void kernel_launch(void* const* d_in, const int* in_sizes, int n_in,
                              void* d_out, int out_size) {
    // z_e_x is always the larger buffer (4x codebook).
    const float* z;
    const float* cb;
    if (in_sizes[0] >= in_sizes[1]) { z = (const float*)d_in[0]; cb = (const float*)d_in[1]; }
    else                            { cb = (const float*)d_in[0]; z = (const float*)d_in[1]; }
    float* out = (float*)d_out;

    cudaFuncSetAttribute(vq_mma_kernel,
                         cudaFuncAttributeMaxDynamicSharedMemorySize, SM_TOTAL);

    prep_kernel<<<KC / 8, 256>>>(cb);
    vq_mma_kernel<<<NQ / MT, 1024, SM_TOTAL>>>(z, out);
    recheckA_kernel<<<1024, 256>>>(z, cb, out);
    fallbackB_kernel<<<256, 256>>>(z, cb, out);
}